// round 5
// baseline (speedup 1.0000x reference)
#include <cuda_runtime.h>
#include <cuda_bf16.h>
#include <math.h>

// Problem constants
#define B     32
#define CIN   512
#define HW    4096          // 64*64
#define MID   32            // 512/16
#define COUT  512
#define TOTAL_CTAS (B * CIN)   // 16384

// Scratch (no cudaMalloc allowed)
__device__ float        g_pooled[B * CIN];  // [B, CIN] means
__device__ unsigned int g_arrive;           // zero-init; reset to 0 at end of each launch
__device__ unsigned int g_done;             // zero-init; reset to 0 at end of each launch

// ---------------------------------------------------------------------------
// Fused kernel.
//  Part A (all 16384 CTAs): global average pool of one (b,c) row — identical
//    to the proven roofline pool: 256 threads x 4 float4 loads + tree reduce.
//    Then publish mean, __threadfence(), atomicAdd(g_arrive).
//  Part B (CTAs 0..31 only, one per batch): spin until g_arrive == 16384,
//    then compute the SE FC chain for batch b = blockIdx.x:
//      phase 1: warp w computes mids {4w..4w+3} (shared pooled loads, 4
//               independent butterflies) -> s_h (ReLU).
//      phase 2: warp w owns outputs [64w, 64w+64), in 2 halves of 32:
//               coalesced LDG of the 32x32 w2 tile -> padded smem transpose
//               (conflict-free STS/LDS) -> 32 FMA per output, sigmoid, store.
//  Reset: last finishing spinner (g_done == 31) zeroes both counters, so the
//  kernel is replay-deterministic under CUDA graph capture.
// ---------------------------------------------------------------------------
__global__ __launch_bounds__(256) void se_fused_kernel(
    const float* __restrict__ x,
    const float* __restrict__ w1, const float* __restrict__ b1,
    const float* __restrict__ w2, const float* __restrict__ b2,
    float* __restrict__ out)
{
    __shared__ float warp_sums[8];
    __shared__ float s_h[MID];
    __shared__ float s_tile[8][32 * 33];   // per-warp padded transpose tile (~34 KB)

    const int tid  = threadIdx.x;
    const int lane = tid & 31;
    const int wid  = tid >> 5;

    // ---------------- Part A: pool one row ----------------
    {
        const int row = blockIdx.x;
        const float4* __restrict__ p =
            reinterpret_cast<const float4*>(x + (size_t)row * HW);

        float4 v0 = p[tid];
        float4 v1 = p[tid + 256];
        float4 v2 = p[tid + 512];
        float4 v3 = p[tid + 768];

        float s = (v0.x + v0.y) + (v0.z + v0.w)
                + (v1.x + v1.y) + (v1.z + v1.w)
                + (v2.x + v2.y) + (v2.z + v2.w)
                + (v3.x + v3.y) + (v3.z + v3.w);

        #pragma unroll
        for (int off = 16; off > 0; off >>= 1)
            s += __shfl_xor_sync(0xFFFFFFFFu, s, off);

        if (lane == 0) warp_sums[wid] = s;
        __syncthreads();

        if (tid == 0) {
            float t = 0.0f;
            #pragma unroll
            for (int i = 0; i < 8; i++) t += warp_sums[i];
            g_pooled[row] = t * (1.0f / (float)HW);
            __threadfence();                       // publish mean (release)
            atomicAdd(&g_arrive, 1u);              // arrive
        }
    }

    if (blockIdx.x >= B) return;                   // non-spinner CTAs done

    // ---------------- Part B: spinner CTA b does FC for batch b -------------
    const int b = blockIdx.x;

    if (tid == 0) {
        while (atomicAdd(&g_arrive, 0u) < (unsigned)TOTAL_CTAS)
            __nanosleep(64);
        __threadfence();                           // acquire
    }
    __syncthreads();

    // Phase 1: warp wid computes mids m0..m0+3
    {
        const int m0 = wid * 4;
        const float* __restrict__ pr = g_pooled + (size_t)b * CIN;
        const float* __restrict__ w1r0 = w1 + (size_t)(m0 + 0) * CIN;
        const float* __restrict__ w1r1 = w1 + (size_t)(m0 + 1) * CIN;
        const float* __restrict__ w1r2 = w1 + (size_t)(m0 + 2) * CIN;
        const float* __restrict__ w1r3 = w1 + (size_t)(m0 + 3) * CIN;

        float a0 = 0.f, a1 = 0.f, a2 = 0.f, a3 = 0.f;
        #pragma unroll
        for (int j = 0; j < 16; j++) {
            const int k = lane + 32 * j;
            const float pv = pr[k];
            a0 = fmaf(pv, w1r0[k], a0);
            a1 = fmaf(pv, w1r1[k], a1);
            a2 = fmaf(pv, w1r2[k], a2);
            a3 = fmaf(pv, w1r3[k], a3);
        }
        #pragma unroll
        for (int off = 16; off > 0; off >>= 1) {
            a0 += __shfl_xor_sync(0xFFFFFFFFu, a0, off);
            a1 += __shfl_xor_sync(0xFFFFFFFFu, a1, off);
            a2 += __shfl_xor_sync(0xFFFFFFFFu, a2, off);
            a3 += __shfl_xor_sync(0xFFFFFFFFu, a3, off);
        }
        if (lane == 0) {
            float h0 = a0 + b1[m0 + 0];
            float h1 = a1 + b1[m0 + 1];
            float h2 = a2 + b1[m0 + 2];
            float h3 = a3 + b1[m0 + 3];
            s_h[m0 + 0] = h0 > 0.f ? h0 : 0.f;
            s_h[m0 + 1] = h1 > 0.f ? h1 : 0.f;
            s_h[m0 + 2] = h2 > 0.f ? h2 : 0.f;
            s_h[m0 + 3] = h3 > 0.f ? h3 : 0.f;
        }
    }
    __syncthreads();

    // Phase 2: warp wid owns outputs [64*wid, 64*wid+64), 2 halves of 32.
    {
        float* __restrict__ tile = s_tile[wid];
        #pragma unroll
        for (int half = 0; half < 2; half++) {
            const int base = wid * 64 + half * 32;

            __syncwarp();
            #pragma unroll
            for (int i = 0; i < 32; i++)          // coalesced LDG, conflict-free STS
                tile[i * 33 + lane] = w2[(size_t)(base + i) * MID + lane];
            __syncwarp();

            float acc = b2[base + lane];
            #pragma unroll
            for (int m = 0; m < MID; m++)         // conflict-free LDS + smem broadcast
                acc = fmaf(tile[lane * 33 + m], s_h[m], acc);

            out[(size_t)b * COUT + base + lane] = 1.0f / (1.0f + __expf(-acc));
        }
    }
    __syncthreads();

    // Reset counters for the next graph replay (last spinner to finish).
    if (tid == 0) {
        unsigned d = atomicAdd(&g_done, 1u);
        if (d == (unsigned)(B - 1)) {
            g_arrive = 0u;
            g_done   = 0u;
            __threadfence();
        }
    }
}

// ---------------------------------------------------------------------------
extern "C" void kernel_launch(void* const* d_in, const int* in_sizes, int n_in,
                              void* d_out, int out_size) {
    const float* x  = (const float*)d_in[0];
    const float* w1 = (const float*)d_in[1];
    const float* b1 = (const float*)d_in[2];
    const float* w2 = (const float*)d_in[3];
    const float* b2 = (const float*)d_in[4];
    float* out = (float*)d_out;

    se_fused_kernel<<<TOTAL_CTAS, 256>>>(x, w1, b1, w2, b2, out);
}

// round 6
// speedup vs baseline: 1.4055x; 1.4055x over previous
#include <cuda_runtime.h>
#include <cuda_bf16.h>
#include <math.h>

// Problem constants
#define B     32
#define CIN   512
#define HW    4096          // 64*64
#define MID   32            // 512/16
#define COUT  512

// Scratch (no cudaMalloc allowed)
__device__ float g_pooled[B * CIN];   // [B, CIN] means

// ---------------------------------------------------------------------------
// Kernel 1: global average pool.  (UNCHANGED — measured 6.9 TB/s, ~86% of HBM)
// One CTA per (b, c) row: 4096 contiguous floats. 256 threads x 4 float4.
// ---------------------------------------------------------------------------
__global__ __launch_bounds__(256) void se_pool_kernel(const float* __restrict__ x) {
    const int row = blockIdx.x;                 // 0 .. B*CIN-1
    const float4* __restrict__ p =
        reinterpret_cast<const float4*>(x + (size_t)row * HW);
    const int tid = threadIdx.x;

    float4 v0 = p[tid];
    float4 v1 = p[tid + 256];
    float4 v2 = p[tid + 512];
    float4 v3 = p[tid + 768];

    float s = (v0.x + v0.y) + (v0.z + v0.w)
            + (v1.x + v1.y) + (v1.z + v1.w)
            + (v2.x + v2.y) + (v2.z + v2.w)
            + (v3.x + v3.y) + (v3.z + v3.w);

    #pragma unroll
    for (int off = 16; off > 0; off >>= 1)
        s += __shfl_xor_sync(0xFFFFFFFFu, s, off);

    __shared__ float warp_sums[8];
    const int lane = tid & 31;
    const int wid  = tid >> 5;
    if (lane == 0) warp_sums[wid] = s;
    __syncthreads();

    if (wid == 0) {
        float t = (lane < 8) ? warp_sums[lane] : 0.0f;
        #pragma unroll
        for (int off = 4; off > 0; off >>= 1)
            t += __shfl_xor_sync(0xFFFFFFFFu, t, off);
        if (lane == 0)
            g_pooled[row] = t * (1.0f / (float)HW);
    }
}

// ---------------------------------------------------------------------------
// Kernel 2: FC bottleneck + ReLU, FC expansion + sigmoid.
// One CTA per batch row b. 512 threads (16 warps). Latency-optimized:
//   Phase 1: warp w computes mids {2w, 2w+1}: strided coalesced loads into
//            2 independent accumulators, one batched butterfly reduce.
//   Phase 2: warp w owns outputs [32w, 32w+32): coalesced LDG of the 32x32
//            w2 tile -> padded smem transpose (conflict-free STS/LDS) ->
//            32 independent FMAs per output. No cross-lane reduce.
// ---------------------------------------------------------------------------
__global__ __launch_bounds__(512) void se_fc_kernel(
    const float* __restrict__ w1, const float* __restrict__ b1,
    const float* __restrict__ w2, const float* __restrict__ b2,
    float* __restrict__ out)
{
    const int b    = blockIdx.x;
    const int tid  = threadIdx.x;
    const int lane = tid & 31;
    const int wid  = tid >> 5;

    __shared__ float s_pooled[CIN];
    __shared__ float s_h[MID];
    __shared__ float s_tile[16][32 * 33 + 1];   // per-warp padded transpose tile

    s_pooled[tid] = g_pooled[b * CIN + tid];

    // Kick off phase-2 weight loads EARLY (independent of pooled data):
    // warp wid owns w2 rows [32*wid, 32*wid+32); coalesced, 1 line per LDG.
    {
        float* __restrict__ tile = s_tile[wid];
        const int base = wid * 32;
        #pragma unroll
        for (int i = 0; i < 32; i++)
            tile[i * 33 + lane] = w2[(size_t)(base + i) * MID + lane];
    }
    __syncthreads();

    // Phase 1: warp wid computes mids {2*wid, 2*wid+1}
    {
        const int m0 = wid * 2;
        const float* __restrict__ w1r0 = w1 + (size_t)(m0 + 0) * CIN;
        const float* __restrict__ w1r1 = w1 + (size_t)(m0 + 1) * CIN;

        float a0 = 0.f, a1 = 0.f;
        #pragma unroll
        for (int j = 0; j < 16; j++) {
            const int k = lane + 32 * j;
            const float pv = s_pooled[k];
            a0 = fmaf(pv, w1r0[k], a0);
            a1 = fmaf(pv, w1r1[k], a1);
        }
        #pragma unroll
        for (int off = 16; off > 0; off >>= 1) {
            a0 += __shfl_xor_sync(0xFFFFFFFFu, a0, off);
            a1 += __shfl_xor_sync(0xFFFFFFFFu, a1, off);
        }
        if (lane == 0) {
            float h0 = a0 + b1[m0 + 0];
            float h1 = a1 + b1[m0 + 1];
            s_h[m0 + 0] = h0 > 0.f ? h0 : 0.f;
            s_h[m0 + 1] = h1 > 0.f ? h1 : 0.f;
        }
    }
    __syncthreads();

    // Phase 2: output o = 32*wid + lane; 32 independent FMAs from smem.
    {
        const float* __restrict__ tile = s_tile[wid];
        const int o = wid * 32 + lane;

        float acc = b2[o];
        #pragma unroll
        for (int m = 0; m < MID; m++)           // tile row conflict-free (33 pad)
            acc = fmaf(tile[lane * 33 + m], s_h[m], acc);

        out[(size_t)b * COUT + o] = 1.0f / (1.0f + __expf(-acc));
    }
}

// ---------------------------------------------------------------------------
extern "C" void kernel_launch(void* const* d_in, const int* in_sizes, int n_in,
                              void* d_out, int out_size) {
    const float* x  = (const float*)d_in[0];
    const float* w1 = (const float*)d_in[1];
    const float* b1 = (const float*)d_in[2];
    const float* w2 = (const float*)d_in[3];
    const float* b2 = (const float*)d_in[4];
    float* out = (float*)d_out;

    se_pool_kernel<<<B * CIN, 256>>>(x);
    se_fc_kernel<<<B, 512>>>(w1, b1, w2, b2, out);
}